// round 7
// baseline (speedup 1.0000x reference)
#include <cuda_runtime.h>
#include <cstdint>

// ---------------- problem constants ----------------
#define BATCH   4
#define CIN     23
#define TT      8
#define HH      128
#define WWID    128
#define LSEQ    8192      // T * Hp * Wp = 8*32*32
#define BL      32768     // BATCH * LSEQ
#define DM      256
#define DINNER  512
#define DPROJ   1064      // 2*512 + 2*16 + 8
#define CONVD   544       // 512 + 32
#define CONVD4  136       // CONVD/4
#define NH      8
#define HD      64
#define DS      16
#define KPATCH  368       // CIN * 4 * 4
#define CHK     128       // scan chunk length
#define NCH     64        // LSEQ / CHK
#define BHN     32        // BATCH * NH

// ---------------- scratch (device globals; no allocation) ----------------
__device__ float g_emb[BL * DM];
__device__ float g_zx[BL * DPROJ];
__device__ float g_xbc[BL * CONVD];
__device__ float g_dtsp[BL * NH];
__device__ float g_dA[BL * NH];
__device__ float g_hloc[BHN * NCH * HD * DS];
__device__ float g_hinit[BHN * NCH * HD * DS];
__device__ float g_dAp[BHN * NCH];
__device__ float g_y[BL * DINNER];
__device__ float g_outseq[BL * DM];
__device__ float g_pwt[KPATCH * DM];        // patch_w transposed [k][d]

// =====================================================================
// 3xTF32 tensor-core GEMM: block 128x128, BK=16, 8 warps (each 32x64).
// hi/lo split precomputed at staging time; inner loop is LDS + MMA only.
// C = A(row-major MxK) * B(row-major KxN)
// acc += a_lo*b_hi + a_hi*b_lo + a_hi*b_hi   (bit-identical to round 6)
// =====================================================================
#define BK 16

__device__ __forceinline__ void mma_tf32(float c[4],
                                         const uint32_t a[4],
                                         uint32_t b0, uint32_t b1)
{
    asm volatile(
        "mma.sync.aligned.m16n8k8.row.col.f32.tf32.tf32.f32 "
        "{%0,%1,%2,%3},{%4,%5,%6,%7},{%8,%9},{%0,%1,%2,%3};"
        : "+f"(c[0]), "+f"(c[1]), "+f"(c[2]), "+f"(c[3])
        : "r"(a[0]), "r"(a[1]), "r"(a[2]), "r"(a[3]), "r"(b0), "r"(b1));
}

__device__ __forceinline__ uint32_t f2tf(float x)
{
    uint32_t r;
    asm("cvt.rna.tf32.f32 %0, %1;" : "=r"(r) : "f"(x));
    return r;
}
__device__ __forceinline__ uint2 split2(float x)
{
    uint32_t hi = f2tf(x);
    uint32_t lo = f2tf(x - __uint_as_float(hi));
    return make_uint2(hi, lo);
}

// A-source functors (return 16B-aligned pointer for 4 consecutive k)
struct ALd {
    const float* A; int K;
    __device__ __forceinline__ const float* p(int m, int k) const {
        return &A[(size_t)m * K + k];
    }
};
struct ALpatch {
    const float* X;
    __device__ __forceinline__ const float* p(int bl, int k) const {
        int b  = bl >> 13;
        int l  = bl & 8191;
        int t  = l >> 10;
        int hw = l & 1023;
        int hp = hw >> 5;
        int wp = hw & 31;
        int c  = k >> 4;
        int i2 = (k >> 2) & 3;
        return &X[((size_t)(((b * CIN + c) * TT + t) * HH + hp * 4 + i2)) * WWID + wp * 4];
    }
};

template <class AL>
__device__ __forceinline__ void gemm_tc(const AL& al, const float* __restrict__ B,
                                        int N, int K, int row0, int col0,
                                        float acc[2][8][4])
{
    // A split plane: (hi,lo) per element, [m][k], pad 20 (conflict-free LDS.64)
    __shared__ __align__(16) uint2 A_sp[128][20];
    // B split plane: uint4 = (hi_k, lo_k, hi_{k+4}, lo_{k+4}) at [ks][lk][c],
    // lk-row stride 130 -> conflict-free LDS.128 quarter-warp phases
    __shared__ __align__(16) uint4 B_sp[2][4][130];

    const int tid  = threadIdx.x;
    const int lane = tid & 31;
    const int warp = tid >> 5;
    const int g    = lane >> 2;          // 0..7
    const int lk   = lane & 3;           // 0..3
    const int wrow = (warp & 3) * 32;
    const int wcol = (warp >> 2) * 64;

#pragma unroll
    for (int mt = 0; mt < 2; mt++)
#pragma unroll
        for (int nt = 0; nt < 8; nt++)
#pragma unroll
            for (int i = 0; i < 4; i++) acc[mt][nt][i] = 0.f;

    const int S = K / BK;   // K is always a multiple of 16 here

    // staging decode (per thread, two quanta each for A and B)
    const int aM0  = tid >> 2;                 // A row (q=0), +64? no: idx>>2 ranges over q
    const int aKq0 = (tid & 3) << 2;           // A k-offset *4
    (void)aM0; (void)aKq0;

    auto loadAraw = [&](int k0, int q) -> float4 {
        int idx = tid + (q << 8);
        int m = idx >> 2, kq = (idx & 3) << 2;
        return *(const float4*)al.p(row0 + m, k0 + kq);
    };
    auto loadBraw = [&](int k0, int q) -> float4 {
        int idx = tid + (q << 8);
        int k = idx >> 5, c4 = (idx & 31) << 2;
        int col = col0 + c4;
        const float* br = &B[(size_t)(k0 + k) * N + col];
        if (col + 3 < N) return *(const float4*)br;
        float4 v = make_float4(0.f, 0.f, 0.f, 0.f);
        if (col + 0 < N) v.x = br[0];
        if (col + 1 < N) v.y = br[1];
        if (col + 2 < N) v.z = br[2];
        return v;
    };
    auto storeA = [&](const float4& raw, int q) {
        int idx = tid + (q << 8);
        int m = idx >> 2, kq = (idx & 3) << 2;
        uint2 s0 = split2(raw.x), s1 = split2(raw.y);
        uint2 s2 = split2(raw.z), s3 = split2(raw.w);
        *(uint4*)&A_sp[m][kq]     = make_uint4(s0.x, s0.y, s1.x, s1.y);
        *(uint4*)&A_sp[m][kq + 2] = make_uint4(s2.x, s2.y, s3.x, s3.y);
    };
    auto storeB = [&](const float4& raw, int q) {
        int idx = tid + (q << 8);
        int k = idx >> 5, c4 = (idx & 31) << 2;
        int ks = k >> 3, lkk = k & 3, half = (k >> 2) & 1;
        uint2* base = (uint2*)&B_sp[ks][lkk][0];
        base[(c4 + 0) * 2 + half] = split2(raw.x);
        base[(c4 + 1) * 2 + half] = split2(raw.y);
        base[(c4 + 2) * 2 + half] = split2(raw.z);
        base[(c4 + 3) * 2 + half] = split2(raw.w);
    };

    float4 pa[2], pb[2];
#pragma unroll
    for (int q = 0; q < 2; q++) { pa[q] = loadAraw(0, q); pb[q] = loadBraw(0, q); }

    for (int s = 0; s < S; s++) {
        if (s > 0) __syncthreads();          // prior compute readers done
#pragma unroll
        for (int q = 0; q < 2; q++) { storeA(pa[q], q); storeB(pb[q], q); }
        if (s + 1 < S) {                     // prefetch next stage (overlaps compute)
            int k0 = (s + 1) * BK;
#pragma unroll
            for (int q = 0; q < 2; q++) { pa[q] = loadAraw(k0, q); pb[q] = loadBraw(k0, q); }
        }
        __syncthreads();

#pragma unroll
        for (int ks = 0; ks < 2; ks++) {
            int kb = ks * 8;
            uint32_t ah[2][4], alo[2][4];
#pragma unroll
            for (int mt = 0; mt < 2; mt++) {
                int r = wrow + mt * 16 + g;
                uint2 t0 = A_sp[r][kb + lk];
                uint2 t1 = A_sp[r + 8][kb + lk];
                uint2 t2 = A_sp[r][kb + lk + 4];
                uint2 t3 = A_sp[r + 8][kb + lk + 4];
                ah[mt][0] = t0.x; alo[mt][0] = t0.y;
                ah[mt][1] = t1.x; alo[mt][1] = t1.y;
                ah[mt][2] = t2.x; alo[mt][2] = t2.y;
                ah[mt][3] = t3.x; alo[mt][3] = t3.y;
            }
#pragma unroll
            for (int nt = 0; nt < 8; nt++) {
                int c = wcol + nt * 8 + g;
                uint4 bq = B_sp[ks][lk][c];   // (hi_k, lo_k, hi_k4, lo_k4)
                mma_tf32(acc[0][nt], alo[0], bq.x, bq.z);   // lo*hi
                mma_tf32(acc[1][nt], alo[1], bq.x, bq.z);
                mma_tf32(acc[0][nt], ah[0],  bq.y, bq.w);   // hi*lo
                mma_tf32(acc[1][nt], ah[1],  bq.y, bq.w);
                mma_tf32(acc[0][nt], ah[0],  bq.x, bq.z);   // hi*hi
                mma_tf32(acc[1][nt], ah[1],  bq.x, bq.z);
            }
        }
    }
    __syncthreads();
}

// ---------------- the four GEMM kernels ----------------

__global__ __launch_bounds__(256, 2) void k_patch(const float* __restrict__ X,
                                                  const float* __restrict__ pb)
{
    const int row0 = blockIdx.y * 128, col0 = blockIdx.x * 128;
    float acc[2][8][4];
    ALpatch al{X};
    gemm_tc(al, g_pwt, DM, KPATCH, row0, col0, acc);

    const int lane = threadIdx.x & 31, warp = threadIdx.x >> 5;
    const int g = lane >> 2, lk = lane & 3;
    const int wrow = (warp & 3) * 32, wcol = (warp >> 2) * 64;
#pragma unroll
    for (int mt = 0; mt < 2; mt++)
#pragma unroll
        for (int i = 0; i < 2; i++) {
            size_t r = (size_t)(row0 + wrow + mt * 16 + g + i * 8);
#pragma unroll
            for (int nt = 0; nt < 8; nt++) {
                int c = col0 + wcol + nt * 8 + 2 * lk;
                float2 v;
                v.x = acc[mt][nt][i * 2 + 0] + pb[c];
                v.y = acc[mt][nt][i * 2 + 1] + pb[c + 1];
                *(float2*)&g_emb[r * DM + c] = v;
            }
        }
}

__global__ __launch_bounds__(256, 2) void k_inproj(const float* __restrict__ Win)
{
    const int row0 = blockIdx.y * 128, col0 = blockIdx.x * 128;
    float acc[2][8][4];
    ALd al{g_emb, DM};
    gemm_tc(al, Win, DPROJ, DM, row0, col0, acc);

    const int lane = threadIdx.x & 31, warp = threadIdx.x >> 5;
    const int g = lane >> 2, lk = lane & 3;
    const int wrow = (warp & 3) * 32, wcol = (warp >> 2) * 64;
#pragma unroll
    for (int mt = 0; mt < 2; mt++)
#pragma unroll
        for (int i = 0; i < 2; i++) {
            size_t r = (size_t)(row0 + wrow + mt * 16 + g + i * 8);
#pragma unroll
            for (int nt = 0; nt < 8; nt++) {
                int c = col0 + wcol + nt * 8 + 2 * lk;
                if (c + 1 < DPROJ) {
                    float2 v;
                    v.x = acc[mt][nt][i * 2 + 0];
                    v.y = acc[mt][nt][i * 2 + 1];
                    *(float2*)&g_zx[r * DPROJ + c] = v;
                }
            }
        }
}

__global__ __launch_bounds__(256, 2) void k_outproj(const float* __restrict__ Wout)
{
    const int row0 = blockIdx.y * 128, col0 = blockIdx.x * 128;
    float acc[2][8][4];
    ALd al{g_y, DINNER};
    gemm_tc(al, Wout, DM, DINNER, row0, col0, acc);

    const int lane = threadIdx.x & 31, warp = threadIdx.x >> 5;
    const int g = lane >> 2, lk = lane & 3;
    const int wrow = (warp & 3) * 32, wcol = (warp >> 2) * 64;
#pragma unroll
    for (int mt = 0; mt < 2; mt++)
#pragma unroll
        for (int i = 0; i < 2; i++) {
            size_t r = (size_t)(row0 + wrow + mt * 16 + g + i * 8);
#pragma unroll
            for (int nt = 0; nt < 8; nt++) {
                int c = col0 + wcol + nt * 8 + 2 * lk;
                float2 v;
                v.x = acc[mt][nt][i * 2 + 0];
                v.y = acc[mt][nt][i * 2 + 1];
                *(float2*)&g_outseq[r * DM + c] = v;
            }
        }
}

__global__ __launch_bounds__(256, 2) void k_unembed(const float* __restrict__ UW,
                                                    const float* __restrict__ ub,
                                                    const float* __restrict__ X,
                                                    float* __restrict__ OUT)
{
    const int row0 = blockIdx.y * 128, col0 = blockIdx.x * 128;
    float acc[2][8][4];
    ALd al{g_outseq, DM};
    gemm_tc(al, UW, KPATCH, DM, row0, col0, acc);

    const int lane = threadIdx.x & 31, warp = threadIdx.x >> 5;
    const int g = lane >> 2, lk = lane & 3;
    const int wrow = (warp & 3) * 32, wcol = (warp >> 2) * 64;
#pragma unroll
    for (int mt = 0; mt < 2; mt++)
#pragma unroll
        for (int i = 0; i < 2; i++) {
            int r  = row0 + wrow + mt * 16 + g + i * 8;
            int b  = r >> 13;
            int l  = r & 8191;
            int t  = l >> 10;
            int hw = l & 1023;
            int hp = hw >> 5;
            int wp = hw & 31;
#pragma unroll
            for (int nt = 0; nt < 8; nt++) {
#pragma unroll
                for (int jj2 = 0; jj2 < 2; jj2++) {
                    int c = col0 + wcol + nt * 8 + 2 * lk + jj2;
                    if (c < KPATCH) {
                        int cc = c >> 4;
                        int ii = (c >> 2) & 3;
                        int jj = c & 3;
                        size_t xi = ((size_t)(((b * CIN + cc) * TT + t) * HH + hp * 4 + ii)) * WWID + wp * 4 + jj;
                        OUT[xi] = acc[mt][nt][i * 2 + jj2] + ub[cc] + X[xi];
                    }
                }
            }
        }
}

// ---------------- patch_w transpose: g_pwt[k][d] = patch_w[d][k] ----------------
__global__ void k_tpw(const float* __restrict__ pw) {
    int idx = blockIdx.x * 256 + threadIdx.x;
    if (idx >= KPATCH * DM) return;
    int k = idx / DM, d = idx % DM;
    g_pwt[idx] = pw[d * KPATCH + k];
}

// ---------------- causal depthwise conv (k=4) + silu over xBC (x4 channels) ----------------
__global__ void k_conv(const float* __restrict__ cw, const float* __restrict__ cb) {
    int idx = blockIdx.x * 256 + threadIdx.x;
    if (idx >= BL * CONVD4) return;
    int c4 = (idx % CONVD4) * 4;
    int bl = idx / CONVD4;
    int l  = bl & (LSEQ - 1);
    float4 w0 = *(const float4*)&cw[(c4 + 0) * 4];
    float4 w1 = *(const float4*)&cw[(c4 + 1) * 4];
    float4 w2 = *(const float4*)&cw[(c4 + 2) * 4];
    float4 w3 = *(const float4*)&cw[(c4 + 3) * 4];
    float4 a  = *(const float4*)&cb[c4];
#define CONV_TAP(K, COMP)                                                      \
    if (l - 3 + K >= 0) {                                                      \
        float4 v = *(const float4*)&g_zx[(size_t)(bl - 3 + K) * DPROJ + DINNER + c4]; \
        a.x = fmaf(v.x, w0.COMP, a.x); a.y = fmaf(v.y, w1.COMP, a.y);          \
        a.z = fmaf(v.z, w2.COMP, a.z); a.w = fmaf(v.w, w3.COMP, a.w);          \
    }
    CONV_TAP(0, x) CONV_TAP(1, y) CONV_TAP(2, z) CONV_TAP(3, w)
#undef CONV_TAP
    float4 o;
    o.x = a.x / (1.f + expf(-a.x));
    o.y = a.y / (1.f + expf(-a.y));
    o.z = a.z / (1.f + expf(-a.z));
    o.w = a.w / (1.f + expf(-a.w));
    *(float4*)&g_xbc[(size_t)bl * CONVD + c4] = o;
}

// ---------------- dt prep: softplus + dA ----------------
__global__ void k_dt(const float* __restrict__ dtb, const float* __restrict__ Alog) {
    int idx = blockIdx.x * 256 + threadIdx.x;
    if (idx >= BL * NH) return;
    int bl = idx >> 3, hd = idx & 7;
    float v  = g_zx[(size_t)bl * DPROJ + (DINNER + CONVD) + hd] + dtb[hd];
    float sp = (v > 20.f) ? v : log1pf(expf(v));
    g_dtsp[idx] = sp;
    float A = -expf(Alog[hd]);
    g_dA[idx] = expf(sp * A);
}

// ---------------- chunked scan: phase A (local scan from zero) ----------------
__global__ __launch_bounds__(64) void k_scan_a() {
    int p     = threadIdx.x;
    int chunk = blockIdx.x;
    int bh    = blockIdx.y;
    int b = bh >> 3, hd = bh & 7;
    float h[16];
#pragma unroll
    for (int n = 0; n < 16; n++) h[n] = 0.f;
    float prod = 1.f;
    int bl0 = b * LSEQ + chunk * CHK;
#pragma unroll 2
    for (int s = 0; s < CHK; s++) {
        int bl = bl0 + s;
        float dA   = g_dA[bl * NH + hd];
        float dtsp = g_dtsp[bl * NH + hd];
        size_t rb = (size_t)bl * CONVD;
        float xv  = g_xbc[rb + hd * HD + p];
        float xdt = xv * dtsp;
        float Bv[16];
        const float4* Bp = (const float4*)&g_xbc[rb + DINNER];
        *(float4*)&Bv[0]  = Bp[0]; *(float4*)&Bv[4]  = Bp[1];
        *(float4*)&Bv[8]  = Bp[2]; *(float4*)&Bv[12] = Bp[3];
#pragma unroll
        for (int n = 0; n < 16; n++) h[n] = fmaf(dA, h[n], xdt * Bv[n]);
        prod *= dA;
    }
    float* dst = &g_hloc[((size_t)(bh * NCH + chunk) * HD + p) * DS];
#pragma unroll
    for (int n = 0; n < 16; n++) dst[n] = h[n];
    if (p == 0) g_dAp[bh * NCH + chunk] = prod;
}

// ---------------- chunked scan: phase B (combine across chunks) ----------------
__global__ __launch_bounds__(64) void k_scan_b() {
    int bh = blockIdx.x;
    int p  = threadIdx.x;
    float s[16];
#pragma unroll
    for (int n = 0; n < 16; n++) s[n] = 0.f;
    for (int c = 0; c < NCH; c++) {
        size_t base = ((size_t)(bh * NCH + c) * HD + p) * DS;
        float dp = g_dAp[bh * NCH + c];
#pragma unroll
        for (int n = 0; n < 16; n++) {
            g_hinit[base + n] = s[n];
            s[n] = fmaf(dp, s[n], g_hloc[base + n]);
        }
    }
}

// ---------------- chunked scan: phase C (rescan with init, emit y) ----------------
__global__ __launch_bounds__(64) void k_scan_c(const float* __restrict__ Dp_) {
    int p     = threadIdx.x;
    int chunk = blockIdx.x;
    int bh    = blockIdx.y;
    int b = bh >> 3, hd = bh & 7;
    float Dp = Dp_[hd];
    float h[16];
    {
        const float* src = &g_hinit[((size_t)(bh * NCH + chunk) * HD + p) * DS];
#pragma unroll
        for (int n = 0; n < 16; n++) h[n] = src[n];
    }
    int bl0 = b * LSEQ + chunk * CHK;
#pragma unroll 2
    for (int s = 0; s < CHK; s++) {
        int bl = bl0 + s;
        float dA   = g_dA[bl * NH + hd];
        float dtsp = g_dtsp[bl * NH + hd];
        size_t rb = (size_t)bl * CONVD;
        float xv  = g_xbc[rb + hd * HD + p];
        float xdt = xv * dtsp;
        float Bv[16], Cv[16];
        const float4* Bp = (const float4*)&g_xbc[rb + DINNER];
        *(float4*)&Bv[0]  = Bp[0]; *(float4*)&Bv[4]  = Bp[1];
        *(float4*)&Bv[8]  = Bp[2]; *(float4*)&Bv[12] = Bp[3];
        const float4* Cp = (const float4*)&g_xbc[rb + DINNER + DS];
        *(float4*)&Cv[0]  = Cp[0]; *(float4*)&Cv[4]  = Cp[1];
        *(float4*)&Cv[8]  = Cp[2]; *(float4*)&Cv[12] = Cp[3];
        float y = 0.f;
#pragma unroll
        for (int n = 0; n < 16; n++) {
            h[n] = fmaf(dA, h[n], xdt * Bv[n]);
            y = fmaf(h[n], Cv[n], y);
        }
        g_y[(size_t)bl * DINNER + hd * HD + p] = y + Dp * xv;
    }
}

// ---------------- gating (silu(z)) + RMSNorm ----------------
__global__ __launch_bounds__(256) void k_gnorm(const float* __restrict__ nw) {
    int bl  = blockIdx.x;
    int tid = threadIdx.x;
    size_t zb = (size_t)bl * DPROJ;
    size_t yb = (size_t)bl * DINNER;
    float z0 = g_zx[zb + tid];
    float y0 = g_y[yb + tid];
    float g0 = y0 * (z0 / (1.f + expf(-z0)));
    float z1 = g_zx[zb + tid + 256];
    float y1 = g_y[yb + tid + 256];
    float g1 = y1 * (z1 / (1.f + expf(-z1)));
    float s = g0 * g0 + g1 * g1;
#pragma unroll
    for (int o = 16; o; o >>= 1) s += __shfl_xor_sync(0xffffffffu, s, o);
    __shared__ float ws[8];
    __shared__ float rr;
    if ((tid & 31) == 0) ws[tid >> 5] = s;
    __syncthreads();
    if (tid == 0) {
        float t = 0.f;
#pragma unroll
        for (int i = 0; i < 8; i++) t += ws[i];
        rr = rsqrtf(t / 512.f + 1e-5f);
    }
    __syncthreads();
    float r = rr;
    g_y[yb + tid]       = g0 * r * nw[tid];
    g_y[yb + tid + 256] = g1 * r * nw[tid + 256];
}

// ---------------- launcher ----------------
extern "C" void kernel_launch(void* const* d_in, const int* in_sizes, int n_in,
                              void* d_out, int out_size)
{
    (void)in_sizes; (void)n_in; (void)out_size;
    const float* x        = (const float*)d_in[0];
    const float* patch_w  = (const float*)d_in[1];
    const float* patch_b  = (const float*)d_in[2];
    const float* W_in     = (const float*)d_in[3];
    const float* conv_w   = (const float*)d_in[4];
    const float* conv_b   = (const float*)d_in[5];
    const float* dt_bias  = (const float*)d_in[6];
    const float* A_log    = (const float*)d_in[7];
    const float* D_param  = (const float*)d_in[8];
    const float* norm_w   = (const float*)d_in[9];
    const float* W_out    = (const float*)d_in[10];
    const float* unemb_w  = (const float*)d_in[11];
    const float* unemb_b  = (const float*)d_in[12];
    float* out = (float*)d_out;

    k_tpw<<<(KPATCH * DM + 255) / 256, 256>>>(patch_w);
    k_patch<<<dim3(DM / 128, BL / 128), 256>>>(x, patch_b);
    k_inproj<<<dim3((DPROJ + 127) / 128, BL / 128), 256>>>(W_in);
    k_conv<<<(BL * CONVD4 + 255) / 256, 256>>>(conv_w, conv_b);
    k_dt<<<(BL * NH + 255) / 256, 256>>>(dt_bias, A_log);
    k_scan_a<<<dim3(NCH, BHN), 64>>>();
    k_scan_b<<<BHN, 64>>>();
    k_scan_c<<<dim3(NCH, BHN), 64>>>(D_param);
    k_gnorm<<<BL, 256>>>(norm_w);
    k_outproj<<<dim3(DM / 128, BL / 128), 256>>>(W_out);
    k_unembed<<<dim3((KPATCH + 127) / 128, BL / 128), 256>>>(unemb_w, unemb_b, x, out);
}

// round 12
// speedup vs baseline: 1.4526x; 1.4526x over previous
#include <cuda_runtime.h>
#include <cstdint>

// ---------------- problem constants ----------------
#define BATCH   4
#define CIN     23
#define TT      8
#define HH      128
#define WWID    128
#define LSEQ    8192      // T * Hp * Wp = 8*32*32
#define BL      32768     // BATCH * LSEQ
#define DM      256
#define DINNER  512
#define DPROJ   1064      // 2*512 + 2*16 + 8
#define CONVD   544       // 512 + 32
#define NH      8
#define HD      64
#define DS      16
#define KPATCH  368       // CIN * 4 * 4
#define CHK     128       // scan chunk length
#define NCH     64        // LSEQ / CHK
#define BHN     32        // BATCH * NH

// ---------------- scratch (device globals; no allocation) ----------------
__device__ float g_emb[BL * DM];
__device__ float g_zx[BL * DPROJ];
__device__ float g_xbc[BL * CONVD];
__device__ float g_dtsp[BL * NH];
__device__ float g_dA[BL * NH];
__device__ float g_hloc[BHN * NCH * HD * DS];
__device__ float g_hinit[BHN * NCH * HD * DS];
__device__ float g_dAp[BHN * NCH];
__device__ float g_y[BL * DINNER];
__device__ float g_outseq[BL * DM];
__device__ float g_pwt[KPATCH * DM];        // patch_w transposed [k][d]

// =====================================================================
// 3xTF32 tensor-core GEMM: block 128x128, BK=16, 8 warps (each 32x64),
// cp.async double-buffered staging. C = A(row-major MxK) * B(row-major KxN)
// Error-compensated: acc += a_lo*b_hi + a_hi*b_lo + a_hi*b_hi
// (verified at 1122 us / rel_err 3.9e-6 in round 6 — byte-identical here)
// =====================================================================
#define BK 16

__device__ __forceinline__ void mma_tf32(float c[4],
                                         const uint32_t a[4],
                                         uint32_t b0, uint32_t b1)
{
    asm volatile(
        "mma.sync.aligned.m16n8k8.row.col.f32.tf32.tf32.f32 "
        "{%0,%1,%2,%3},{%4,%5,%6,%7},{%8,%9},{%0,%1,%2,%3};"
        : "+f"(c[0]), "+f"(c[1]), "+f"(c[2]), "+f"(c[3])
        : "r"(a[0]), "r"(a[1]), "r"(a[2]), "r"(a[3]), "r"(b0), "r"(b1));
}

__device__ __forceinline__ uint32_t f2tf(float x)
{
    uint32_t r;
    asm("cvt.rna.tf32.f32 %0, %1;" : "=r"(r) : "f"(x));
    return r;
}
__device__ __forceinline__ void split_tf32(uint32_t raw, uint32_t& hi, uint32_t& lo)
{
    float x = __uint_as_float(raw);
    hi = f2tf(x);
    lo = f2tf(x - __uint_as_float(hi));
}

__device__ __forceinline__ void cp16(uint32_t smem_dst, const void* gsrc, bool pred)
{
    int sz = pred ? 16 : 0;
    asm volatile("cp.async.ca.shared.global [%0], [%1], 16, %2;\n"
                 :: "r"(smem_dst), "l"(gsrc), "r"(sz));
}

// A-source functors (return 16B-aligned pointer for 4 consecutive k)
struct ALd {
    const float* A; int K;
    __device__ __forceinline__ const float* p(int m, int k) const {
        return &A[(size_t)m * K + k];
    }
};
struct ALpatch {
    const float* X;
    __device__ __forceinline__ const float* p(int bl, int k) const {
        int b  = bl >> 13;
        int l  = bl & 8191;
        int t  = l >> 10;
        int hw = l & 1023;
        int hp = hw >> 5;
        int wp = hw & 31;
        int c  = k >> 4;
        int i2 = (k >> 2) & 3;
        return &X[((size_t)(((b * CIN + c) * TT + t) * HH + hp * 4 + i2)) * WWID + wp * 4];
    }
};

template <class AL>
__device__ __forceinline__ void gemm_tc(const AL& al, const float* __restrict__ B,
                                        int N, int K, int row0, int col0,
                                        float acc[2][8][4])
{
    __shared__ __align__(16) uint32_t As[2][128][20];   // [m][k] padded to 20 words
    __shared__ __align__(16) uint32_t Bs[2][BK][132];   // [k][n] padded to 132 words

    const int tid  = threadIdx.x;
    const int lane = tid & 31;
    const int warp = tid >> 5;
    const int g    = lane >> 2;          // 0..7
    const int lk   = lane & 3;           // 0..3
    const int wrow = (warp & 3) * 32;
    const int wcol = (warp >> 2) * 64;

#pragma unroll
    for (int mt = 0; mt < 2; mt++)
#pragma unroll
        for (int nt = 0; nt < 8; nt++)
#pragma unroll
            for (int i = 0; i < 4; i++) acc[mt][nt][i] = 0.f;

    const int S = K / BK;   // K is always a multiple of 16 here

    auto load_stage = [&](int s, int buf) {
        int k0 = s * BK;
        // A: 128x16 floats = 512 x 16B, 2 per thread
#pragma unroll
        for (int q = 0; q < 2; q++) {
            int idx = tid + q * 256;
            int m = idx >> 2, kq = idx & 3;
            uint32_t dst = (uint32_t)__cvta_generic_to_shared(&As[buf][m][kq * 4]);
            cp16(dst, al.p(row0 + m, k0 + kq * 4), true);
        }
        // B: 16x128 floats = 512 x 16B, 2 per thread
#pragma unroll
        for (int q = 0; q < 2; q++) {
            int idx = tid + q * 256;
            int k = idx >> 5, c4 = idx & 31;
            int col = col0 + c4 * 4;
            uint32_t dst = (uint32_t)__cvta_generic_to_shared(&Bs[buf][k][c4 * 4]);
            cp16(dst, &B[(size_t)(k0 + k) * N + col], col + 3 < N);
        }
        asm volatile("cp.async.commit_group;\n");
    };

    load_stage(0, 0);
    for (int s = 0; s < S; s++) {
        int buf = s & 1;
        if (s + 1 < S) {
            load_stage(s + 1, buf ^ 1);
            asm volatile("cp.async.wait_group 1;\n");
        } else {
            asm volatile("cp.async.wait_group 0;\n");
        }
        __syncthreads();

#pragma unroll
        for (int ks = 0; ks < 2; ks++) {
            int kb = ks * 8;
            uint32_t ah[2][4], alo[2][4];
#pragma unroll
            for (int mt = 0; mt < 2; mt++) {
                int r = wrow + mt * 16 + g;
                split_tf32(As[buf][r][kb + lk],          ah[mt][0], alo[mt][0]);
                split_tf32(As[buf][r + 8][kb + lk],      ah[mt][1], alo[mt][1]);
                split_tf32(As[buf][r][kb + lk + 4],      ah[mt][2], alo[mt][2]);
                split_tf32(As[buf][r + 8][kb + lk + 4],  ah[mt][3], alo[mt][3]);
            }
#pragma unroll
            for (int nt = 0; nt < 8; nt++) {
                int c = wcol + nt * 8 + g;
                uint32_t bh0, bl0, bh1, bl1;
                split_tf32(Bs[buf][kb + lk][c],     bh0, bl0);
                split_tf32(Bs[buf][kb + lk + 4][c], bh1, bl1);
                // compensated: lo*hi + hi*lo + hi*hi
                mma_tf32(acc[0][nt], alo[0], bh0, bh1);
                mma_tf32(acc[1][nt], alo[1], bh0, bh1);
                mma_tf32(acc[0][nt], ah[0],  bl0, bl1);
                mma_tf32(acc[1][nt], ah[1],  bl0, bl1);
                mma_tf32(acc[0][nt], ah[0],  bh0, bh1);
                mma_tf32(acc[1][nt], ah[1],  bh0, bh1);
            }
        }
        __syncthreads();
    }
}

// ---------------- the four GEMM kernels ----------------

__global__ __launch_bounds__(256, 2) void k_patch(const float* __restrict__ X,
                                                  const float* __restrict__ pb)
{
    const int row0 = blockIdx.y * 128, col0 = blockIdx.x * 128;
    float acc[2][8][4];
    ALpatch al{X};
    gemm_tc(al, g_pwt, DM, KPATCH, row0, col0, acc);

    const int lane = threadIdx.x & 31, warp = threadIdx.x >> 5;
    const int g = lane >> 2, lk = lane & 3;
    const int wrow = (warp & 3) * 32, wcol = (warp >> 2) * 64;
#pragma unroll
    for (int mt = 0; mt < 2; mt++)
#pragma unroll
        for (int i = 0; i < 2; i++) {
            size_t r = (size_t)(row0 + wrow + mt * 16 + g + i * 8);
#pragma unroll
            for (int nt = 0; nt < 8; nt++) {
                int c = col0 + wcol + nt * 8 + 2 * lk;
                float2 v;
                v.x = acc[mt][nt][i * 2 + 0] + pb[c];
                v.y = acc[mt][nt][i * 2 + 1] + pb[c + 1];
                *(float2*)&g_emb[r * DM + c] = v;
            }
        }
}

__global__ __launch_bounds__(256, 2) void k_inproj(const float* __restrict__ Win)
{
    const int row0 = blockIdx.y * 128, col0 = blockIdx.x * 128;
    float acc[2][8][4];
    ALd al{g_emb, DM};
    gemm_tc(al, Win, DPROJ, DM, row0, col0, acc);

    const int lane = threadIdx.x & 31, warp = threadIdx.x >> 5;
    const int g = lane >> 2, lk = lane & 3;
    const int wrow = (warp & 3) * 32, wcol = (warp >> 2) * 64;
#pragma unroll
    for (int mt = 0; mt < 2; mt++)
#pragma unroll
        for (int i = 0; i < 2; i++) {
            size_t r = (size_t)(row0 + wrow + mt * 16 + g + i * 8);
#pragma unroll
            for (int nt = 0; nt < 8; nt++) {
                int c = col0 + wcol + nt * 8 + 2 * lk;
                if (c + 1 < DPROJ) {
                    float2 v;
                    v.x = acc[mt][nt][i * 2 + 0];
                    v.y = acc[mt][nt][i * 2 + 1];
                    *(float2*)&g_zx[r * DPROJ + c] = v;
                }
            }
        }
}

__global__ __launch_bounds__(256, 2) void k_outproj(const float* __restrict__ Wout)
{
    const int row0 = blockIdx.y * 128, col0 = blockIdx.x * 128;
    float acc[2][8][4];
    ALd al{g_y, DINNER};
    gemm_tc(al, Wout, DM, DINNER, row0, col0, acc);

    const int lane = threadIdx.x & 31, warp = threadIdx.x >> 5;
    const int g = lane >> 2, lk = lane & 3;
    const int wrow = (warp & 3) * 32, wcol = (warp >> 2) * 64;
#pragma unroll
    for (int mt = 0; mt < 2; mt++)
#pragma unroll
        for (int i = 0; i < 2; i++) {
            size_t r = (size_t)(row0 + wrow + mt * 16 + g + i * 8);
#pragma unroll
            for (int nt = 0; nt < 8; nt++) {
                int c = col0 + wcol + nt * 8 + 2 * lk;
                float2 v;
                v.x = acc[mt][nt][i * 2 + 0];
                v.y = acc[mt][nt][i * 2 + 1];
                *(float2*)&g_outseq[r * DM + c] = v;
            }
        }
}

__global__ __launch_bounds__(256, 2) void k_unembed(const float* __restrict__ UW,
                                                    const float* __restrict__ ub,
                                                    const float* __restrict__ X,
                                                    float* __restrict__ OUT)
{
    const int row0 = blockIdx.y * 128, col0 = blockIdx.x * 128;
    float acc[2][8][4];
    ALd al{g_outseq, DM};
    gemm_tc(al, UW, KPATCH, DM, row0, col0, acc);

    const int lane = threadIdx.x & 31, warp = threadIdx.x >> 5;
    const int g = lane >> 2, lk = lane & 3;
    const int wrow = (warp & 3) * 32, wcol = (warp >> 2) * 64;
#pragma unroll
    for (int mt = 0; mt < 2; mt++)
#pragma unroll
        for (int i = 0; i < 2; i++) {
            int r  = row0 + wrow + mt * 16 + g + i * 8;
            int b  = r >> 13;
            int l  = r & 8191;
            int t  = l >> 10;
            int hw = l & 1023;
            int hp = hw >> 5;
            int wp = hw & 31;
#pragma unroll
            for (int nt = 0; nt < 8; nt++) {
#pragma unroll
                for (int jj2 = 0; jj2 < 2; jj2++) {
                    int c = col0 + wcol + nt * 8 + 2 * lk + jj2;
                    if (c < KPATCH) {
                        int cc = c >> 4;
                        int ii = (c >> 2) & 3;
                        int jj = c & 3;
                        size_t xi = ((size_t)(((b * CIN + cc) * TT + t) * HH + hp * 4 + ii)) * WWID + wp * 4 + jj;
                        OUT[xi] = acc[mt][nt][i * 2 + jj2] + ub[cc] + X[xi];
                    }
                }
            }
        }
}

// ---------------- patch_w transpose: g_pwt[k][d] = patch_w[d][k] ----------------
__global__ void k_tpw(const float* __restrict__ pw) {
    int idx = blockIdx.x * 256 + threadIdx.x;
    if (idx >= KPATCH * DM) return;
    int k = idx / DM, d = idx % DM;
    g_pwt[idx] = pw[d * KPATCH + k];
}

// ---------------- causal depthwise conv (k=4) + silu over xBC ----------------
// Two consecutive l per thread: 5 tap-row loads serve 2 outputs (was 8),
// one float4 weight load replaces 4 scalars. FMA order per output identical
// to the round-6 version -> bit-identical results.
__global__ void k_conv(const float* __restrict__ cw, const float* __restrict__ cb) {
    int idx = blockIdx.x * 256 + threadIdx.x;
    if (idx >= (BL / 2) * CONVD) return;
    int c  = idx % CONVD;
    int pr = idx / CONVD;          // pair index
    int bl = pr * 2;               // even bl; bl+1 same sequence (LSEQ even)
    int l  = bl & (LSEQ - 1);

    float4 w = *(const float4*)&cw[c * 4];
    float r[5];
#pragma unroll
    for (int d = 0; d < 5; d++) {
        int ll = l - 3 + d;
        r[d] = (ll >= 0) ? g_zx[(size_t)(bl - 3 + d) * DPROJ + DINNER + c] : 0.f;
    }
    float bias = cb[c];
    // output at bl   : taps r[0..3] (k=0..3)
    float a0 = bias;
    a0 = fmaf(r[0], w.x, a0); a0 = fmaf(r[1], w.y, a0);
    a0 = fmaf(r[2], w.z, a0); a0 = fmaf(r[3], w.w, a0);
    // output at bl+1 : taps r[1..4]
    float a1 = bias;
    a1 = fmaf(r[1], w.x, a1); a1 = fmaf(r[2], w.y, a1);
    a1 = fmaf(r[3], w.z, a1); a1 = fmaf(r[4], w.w, a1);

    g_xbc[(size_t)bl * CONVD + c]       = a0 / (1.f + expf(-a0));
    g_xbc[(size_t)(bl + 1) * CONVD + c] = a1 / (1.f + expf(-a1));
}

// ---------------- dt prep: softplus + dA ----------------
__global__ void k_dt(const float* __restrict__ dtb, const float* __restrict__ Alog) {
    int idx = blockIdx.x * 256 + threadIdx.x;
    if (idx >= BL * NH) return;
    int bl = idx >> 3, hd = idx & 7;
    float v  = g_zx[(size_t)bl * DPROJ + (DINNER + CONVD) + hd] + dtb[hd];
    float sp = (v > 20.f) ? v : log1pf(expf(v));
    g_dtsp[idx] = sp;
    float A = -expf(Alog[hd]);
    g_dA[idx] = expf(sp * A);
}

// ---------------- chunked scan: phase A (local scan from zero) ----------------
__global__ __launch_bounds__(64) void k_scan_a() {
    int p     = threadIdx.x;
    int chunk = blockIdx.x;
    int bh    = blockIdx.y;
    int b = bh >> 3, hd = bh & 7;
    float h[16];
#pragma unroll
    for (int n = 0; n < 16; n++) h[n] = 0.f;
    float prod = 1.f;
    int bl0 = b * LSEQ + chunk * CHK;
#pragma unroll 2
    for (int s = 0; s < CHK; s++) {
        int bl = bl0 + s;
        float dA   = g_dA[bl * NH + hd];
        float dtsp = g_dtsp[bl * NH + hd];
        size_t rb = (size_t)bl * CONVD;
        float xv  = g_xbc[rb + hd * HD + p];
        float xdt = xv * dtsp;
        float Bv[16];
        const float4* Bp = (const float4*)&g_xbc[rb + DINNER];
        *(float4*)&Bv[0]  = Bp[0]; *(float4*)&Bv[4]  = Bp[1];
        *(float4*)&Bv[8]  = Bp[2]; *(float4*)&Bv[12] = Bp[3];
#pragma unroll
        for (int n = 0; n < 16; n++) h[n] = fmaf(dA, h[n], xdt * Bv[n]);
        prod *= dA;
    }
    float* dst = &g_hloc[((size_t)(bh * NCH + chunk) * HD + p) * DS];
#pragma unroll
    for (int n = 0; n < 16; n++) dst[n] = h[n];
    if (p == 0) g_dAp[bh * NCH + chunk] = prod;
}

// ---------------- chunked scan: phase B (combine across chunks) ----------------
__global__ __launch_bounds__(64) void k_scan_b() {
    int bh = blockIdx.x;
    int p  = threadIdx.x;
    float s[16];
#pragma unroll
    for (int n = 0; n < 16; n++) s[n] = 0.f;
    for (int c = 0; c < NCH; c++) {
        size_t base = ((size_t)(bh * NCH + c) * HD + p) * DS;
        float dp = g_dAp[bh * NCH + c];
#pragma unroll
        for (int n = 0; n < 16; n++) {
            g_hinit[base + n] = s[n];
            s[n] = fmaf(dp, s[n], g_hloc[base + n]);
        }
    }
}

// ---------------- chunked scan: phase C (rescan with init, emit y) ----------------
__global__ __launch_bounds__(64) void k_scan_c(const float* __restrict__ Dp_) {
    int p     = threadIdx.x;
    int chunk = blockIdx.x;
    int bh    = blockIdx.y;
    int b = bh >> 3, hd = bh & 7;
    float Dp = Dp_[hd];
    float h[16];
    {
        const float* src = &g_hinit[((size_t)(bh * NCH + chunk) * HD + p) * DS];
#pragma unroll
        for (int n = 0; n < 16; n++) h[n] = src[n];
    }
    int bl0 = b * LSEQ + chunk * CHK;
#pragma unroll 2
    for (int s = 0; s < CHK; s++) {
        int bl = bl0 + s;
        float dA   = g_dA[bl * NH + hd];
        float dtsp = g_dtsp[bl * NH + hd];
        size_t rb = (size_t)bl * CONVD;
        float xv  = g_xbc[rb + hd * HD + p];
        float xdt = xv * dtsp;
        float Bv[16], Cv[16];
        const float4* Bp = (const float4*)&g_xbc[rb + DINNER];
        *(float4*)&Bv[0]  = Bp[0]; *(float4*)&Bv[4]  = Bp[1];
        *(float4*)&Bv[8]  = Bp[2]; *(float4*)&Bv[12] = Bp[3];
        const float4* Cp = (const float4*)&g_xbc[rb + DINNER + DS];
        *(float4*)&Cv[0]  = Cp[0]; *(float4*)&Cv[4]  = Cp[1];
        *(float4*)&Cv[8]  = Cp[2]; *(float4*)&Cv[12] = Cp[3];
        float y = 0.f;
#pragma unroll
        for (int n = 0; n < 16; n++) {
            h[n] = fmaf(dA, h[n], xdt * Bv[n]);
            y = fmaf(h[n], Cv[n], y);
        }
        g_y[(size_t)bl * DINNER + hd * HD + p] = y + Dp * xv;
    }
}

// ---------------- gating (silu(z)) + RMSNorm ----------------
__global__ __launch_bounds__(256) void k_gnorm(const float* __restrict__ nw) {
    int bl  = blockIdx.x;
    int tid = threadIdx.x;
    size_t zb = (size_t)bl * DPROJ;
    size_t yb = (size_t)bl * DINNER;
    float z0 = g_zx[zb + tid];
    float y0 = g_y[yb + tid];
    float g0 = y0 * (z0 / (1.f + expf(-z0)));
    float z1 = g_zx[zb + tid + 256];
    float y1 = g_y[yb + tid + 256];
    float g1 = y1 * (z1 / (1.f + expf(-z1)));
    float s = g0 * g0 + g1 * g1;
#pragma unroll
    for (int o = 16; o; o >>= 1) s += __shfl_xor_sync(0xffffffffu, s, o);
    __shared__ float ws[8];
    __shared__ float rr;
    if ((tid & 31) == 0) ws[tid >> 5] = s;
    __syncthreads();
    if (tid == 0) {
        float t = 0.f;
#pragma unroll
        for (int i = 0; i < 8; i++) t += ws[i];
        rr = rsqrtf(t / 512.f + 1e-5f);
    }
    __syncthreads();
    float r = rr;
    g_y[yb + tid]       = g0 * r * nw[tid];
    g_y[yb + tid + 256] = g1 * r * nw[tid + 256];
}

// ---------------- launcher ----------------
extern "C" void kernel_launch(void* const* d_in, const int* in_sizes, int n_in,
                              void* d_out, int out_size)
{
    (void)in_sizes; (void)n_in; (void)out_size;
    const float* x        = (const float*)d_in[0];
    const float* patch_w  = (const float*)d_in[1];
    const float* patch_b  = (const float*)d_in[2];
    const float* W_in     = (const float*)d_in[3];
    const float* conv_w   = (const float*)d_in[4];
    const float* conv_b   = (const float*)d_in[5];
    const float* dt_bias  = (const float*)d_in[6];
    const float* A_log    = (const float*)d_in[7];
    const float* D_param  = (const float*)d_in[8];
    const float* norm_w   = (const float*)d_in[9];
    const float* W_out    = (const float*)d_in[10];
    const float* unemb_w  = (const float*)d_in[11];
    const float* unemb_b  = (const float*)d_in[12];
    float* out = (float*)d_out;

    // k_tpw launched 3x (idempotent, ~2us each): shifts the GEMM kernels into
    // the ncu capture slot (-s 5 -c 1) so we finally profile gemm_tc instead
    // of k_conv. Determinism unaffected: same work, same output, every call.
    k_tpw<<<(KPATCH * DM + 255) / 256, 256>>>(patch_w);
    k_tpw<<<(KPATCH * DM + 255) / 256, 256>>>(patch_w);
    k_tpw<<<(KPATCH * DM + 255) / 256, 256>>>(patch_w);
    k_patch<<<dim3(DM / 128, BL / 128), 256>>>(x, patch_b);
    k_inproj<<<dim3((DPROJ + 127) / 128, BL / 128), 256>>>(W_in);
    k_conv<<<((BL / 2) * CONVD + 255) / 256, 256>>>(conv_w, conv_b);
    k_dt<<<(BL * NH + 255) / 256, 256>>>(dt_bias, A_log);
    k_scan_a<<<dim3(NCH, BHN), 64>>>();
    k_scan_b<<<BHN, 64>>>();
    k_scan_c<<<dim3(NCH, BHN), 64>>>(D_param);
    k_gnorm<<<BL, 256>>>(norm_w);
    k_outproj<<<dim3(DM / 128, BL / 128), 256>>>(W_out);
    k_unembed<<<dim3((KPATCH + 127) / 128, BL / 128), 256>>>(unemb_w, unemb_b, x, out);
}